// round 8
// baseline (speedup 1.0000x reference)
#include <cuda_runtime.h>
#include <math.h>

#define Bb 64
#define Tt 2048
#define Vv 256
#define Uu 256
#define NEGV (-1e30f)

__device__ float g_d[(size_t)Bb * Tt * 256];   // d[b,t,i] = logits[b,t,tgt[i]] - logits[b,t,0]
__device__ float g_Cpart[Bb * 256];            // per-8-row blank-logp partials
__device__ float g_nll[Bb];

__device__ __forceinline__ void cp16(unsigned sa, const float* g) {
    asm volatile("cp.async.cg.shared.global [%0], [%1], 16;\n" :: "r"(sa), "l"(g) : "memory");
}
__device__ __forceinline__ void cpcommit() {
    asm volatile("cp.async.commit_group;\n" ::: "memory");
}
template<int N> __device__ __forceinline__ void cpwait() {
    asm volatile("cp.async.wait_group %0;\n" :: "n"(N) : "memory");
}
__device__ __forceinline__ void strel(unsigned a, int v) {
    asm volatile("st.release.cta.shared.b32 [%0], %1;" :: "r"(a), "r"(v) : "memory");
}
__device__ __forceinline__ void spinwait(unsigned a, int need) {
    int v;
    do { asm volatile("ld.acquire.cta.shared.b32 %0, [%1];" : "=r"(v) : "r"(a) : "memory"); } while (v < need);
}

// ---------------------------------------------------------------------------
// Kernel 1: fused lse + emission-delta gather + blank-logp partial sums.
// (identical to R4/R7: ~38us)
// ---------------------------------------------------------------------------
#define GB_ROWS 64
__global__ void __launch_bounds__(256) gather_kernel(const float* __restrict__ logits,
                                                     const int*  __restrict__ targets,
                                                     const int*  __restrict__ loglen) {
    __shared__ int   sTgt[Uu];
    __shared__ float sRow[8][4][Vv];

    const int b  = blockIdx.y;
    const int c  = blockIdx.x;
    const int L  = loglen[b];
    const int t0 = c * GB_ROWS;
    if (t0 >= L) return;

    const int tid = threadIdx.x, w = tid >> 5, lane = tid & 31;
    sTgt[tid] = targets[b * Uu + tid];
    __syncthreads();

    const int tbase = t0 + w * 8;
    if (tbase >= L) return;
    int nrows = L - tbase; if (nrows > 8) nrows = 8;

    const float* lg   = logits + ((size_t)b * Tt + tbase) * Vv;
    float*       dOut = g_d    + ((size_t)b * Tt + tbase) * 256;

#pragma unroll
    for (int p = 0; p < 3; ++p) {
        if (p < nrows) {
            unsigned sa = (unsigned)__cvta_generic_to_shared(&sRow[w][p][lane * 8]);
            const float* g = lg + (size_t)p * Vv + lane * 8;
            cp16(sa, g);
            cp16(sa + 16, g + 4);
        }
        cpcommit();
    }

    float cb = 0.0f;
    for (int k = 0; k < nrows; ++k) {
        int pf = k + 3;
        if (pf < nrows) {
            unsigned sa = (unsigned)__cvta_generic_to_shared(&sRow[w][pf & 3][lane * 8]);
            const float* g = lg + (size_t)pf * Vv + lane * 8;
            cp16(sa, g);
            cp16(sa + 16, g + 4);
        }
        cpcommit();
        cpwait<3>();
        __syncwarp();

        const float* r = sRow[w][k & 3];
        float4 v0 = *(const float4*)&r[lane * 4];
        float4 v1 = *(const float4*)&r[128 + lane * 4];
        float s = __expf(v0.x) + __expf(v0.y) + __expf(v0.z) + __expf(v0.w)
                + __expf(v1.x) + __expf(v1.y) + __expf(v1.z) + __expf(v1.w);
#pragma unroll
        for (int o = 16; o; o >>= 1) s += __shfl_xor_sync(0xffffffffu, s, o);
        float lse = __logf(s);
        float r0  = __shfl_sync(0xffffffffu, v0.x, 0);
        cb += r0 - lse;

        int4 tg0 = *(const int4*)&sTgt[lane * 8];
        int4 tg1 = *(const int4*)&sTgt[lane * 8 + 4];
        float4 d0, d1;
        d0.x = r[tg0.x] - r0;  d0.y = r[tg0.y] - r0;
        d0.z = r[tg0.z] - r0;  d0.w = r[tg0.w] - r0;
        d1.x = r[tg1.x] - r0;  d1.y = r[tg1.y] - r0;
        d1.z = r[tg1.z] - r0;  d1.w = r[tg1.w] - r0;

        *(float4*)&dOut[(size_t)k * 256 + lane * 8]     = d0;
        *(float4*)&dOut[(size_t)k * 256 + lane * 8 + 4] = d1;
        __syncwarp();
    }
    if (lane == 0) g_Cpart[b * 256 + (tbase >> 3)] = cb;
}

// ---------------------------------------------------------------------------
// Kernel 2: Viterbi DP, 2 warps per batch with pipeline skew (as R7), but the
// register buffer is 4-phase with LDS prefetch TWO steps ahead, so the 29-cyc
// LDS latency is fully hidden behind two step-times.
// ---------------------------------------------------------------------------
#define DPGc 6
__global__ void __launch_bounds__(64, 1) dp_kernel(const int* __restrict__ targets,
                                                   const int* __restrict__ loglen,
                                                   const int* __restrict__ tgtlen) {
    __shared__ float sBnd[Tt + 8];
    __shared__ float sRing[2][32 * 128];
    __shared__ float sDump[32];
    __shared__ int   sProg;

    const int tid  = threadIdx.x;
    const int wid  = tid >> 5;
    const int lane = tid & 31;
    const int b    = blockIdx.x;
    const int L    = loglen[b];
    const int Ut   = tgtlen[b];
    const int l4   = lane * 4;
    const int pbase = wid * 128 + l4;            // global pair index base
    const float* __restrict__ emB = g_d + (size_t)b * Tt * 256 + wid * 128;
    float* ring = sRing[wid];
    const unsigned ringB = (unsigned)__cvta_generic_to_shared(ring);
    const unsigned bndB  = (unsigned)__cvta_generic_to_shared(sBnd);
    const unsigned progA = (unsigned)__cvta_generic_to_shared(&sProg);

    if (tid == 0) { sProg = 0; sBnd[0] = NEGV; }
    __syncthreads();

    float gate[4];
    {
        int prev = (pbase == 0) ? -1 : targets[b * Uu + pbase - 1];
#pragma unroll
        for (int j = 0; j < 4; ++j) {
            int cur = targets[b * Uu + pbase + j];
            gate[j] = (pbase + j >= 1 && cur != prev) ? 0.0f : NEGV;
            prev = cur;
        }
    }

    float E[4], O[4];
#pragma unroll
    for (int j = 0; j < 4; ++j) { E[j] = NEGV; O[j] = NEGV; }
    if (tid == 0) E[0] = 0.0f;                   // alpha_hat seed
    float Eex = NEGV, pO_cur = NEGV;
    const float pOmask = (lane == 0) ? NEGV : 0.0f;

    // branch-free boundary store: lane31 -> bnd slot, others -> private dump
    const unsigned stBase = (lane == 31) ? bndB
                           : (unsigned)__cvta_generic_to_shared(&sDump[lane]);
    const unsigned stStep = (lane == 31) ? 4u : 0u;

#define ISSUEG(ROW0)                                                          \
    {                                                                         \
        _Pragma("unroll")                                                     \
        for (int r_ = 0; r_ < 4; ++r_) {                                      \
            int row_ = (ROW0) + r_;                                           \
            if (row_ < L) {                                                   \
                unsigned sa_ = ringB + ((((unsigned)row_ & 31u) << 7) + (unsigned)l4) * 4u; \
                cp16(sa_, emB + (size_t)row_ * 256 + l4);                     \
            }                                                                 \
        }                                                                     \
        cpcommit();                                                           \
    }

    // prologue: groups 0..5 (rows 0..23; L >= 1024)
#pragma unroll
    for (int g2 = 0; g2 < DPGc; ++g2) ISSUEG(g2 * 4);
    cpwait<DPGc - 2>();                          // groups 0,1 complete: rows 0..7

    // 4-phase register buffer, prefetch distance 2
    float buf[4][4];
    *(float4*)&buf[0][0] = *(const float4*)(ring + l4);            // row 0
    *(float4*)&buf[1][0] = *(const float4*)(ring + (1 << 7) + l4); // row 1

    const int ncfull = L >> 5;
    const int rem32  = L & 31;
    int blk = 0;

#define SUB0(T)                                                               \
    {                                                                         \
        const float* sp_ = ring + ((((T) + 2) & 31) << 7) + l4;               \
        *(float4*)&buf[((T) + 2) & 3][0] = *(const float4*)sp_;               \
        const float* dv = buf[(T) & 3];                                       \
        float e3 = E[3], o3 = O[3];                                           \
        float O3n = fmaxf(fmaxf(o3, e3), O[2] + gate[3]) + dv[3];             \
        float E3n = fmaxf(e3, O[2]);                                          \
        float nextPO = __shfl_up_sync(0xffffffffu, O3n, 1);                   \
        unsigned dst_ = stBase + (unsigned)((T) + 1) * stStep;                \
        asm volatile("st.shared.b32 [%0], %1;" :: "r"(dst_), "f"(O3n));       \
        float pO = pO_cur;                                                    \
        _Pragma("unroll")                                                     \
        for (int j = 0; j < 3; ++j) {                                         \
            float e = E[j], o = O[j];                                         \
            E[j] = fmaxf(e, pO);                                              \
            O[j] = fmaxf(fmaxf(o, e), pO + gate[j]) + dv[j];                  \
            pO = o;                                                           \
        }                                                                     \
        E[3] = E3n; O[3] = O3n;                                               \
        pO_cur = nextPO + pOmask;                                             \
    }

#define SUB1(T)                                                               \
    {                                                                         \
        const float* sp_ = ring + ((((T) + 2) & 31) << 7) + l4;               \
        *(float4*)&buf[((T) + 2) & 3][0] = *(const float4*)sp_;               \
        float bn = sBnd[(T) + 1];                                             \
        const float* dv = buf[(T) & 3];                                       \
        float e3 = E[3], o3 = O[3];                                           \
        float O3n = fmaxf(fmaxf(o3, e3), O[2] + gate[3]) + dv[3];             \
        float E3n = fmaxf(e3, O[2]);                                          \
        float nextPO = __shfl_up_sync(0xffffffffu, O3n, 1);                   \
        Eex = fmaxf(Eex, o3);                                                 \
        float pO = pO_cur;                                                    \
        _Pragma("unroll")                                                     \
        for (int j = 0; j < 3; ++j) {                                         \
            float e = E[j], o = O[j];                                         \
            E[j] = fmaxf(e, pO);                                              \
            O[j] = fmaxf(fmaxf(o, e), pO + gate[j]) + dv[j];                  \
            pO = o;                                                           \
        }                                                                     \
        E[3] = E3n; O[3] = O3n;                                               \
        pO_cur = (lane == 0) ? bn : nextPO;                                   \
    }

    if (wid == 0) {
        for (int c = 0; c < ncfull; ++c) {
            for (int q = 0; q < 8; ++q, ++blk) {
                ISSUEG((blk + DPGc) * 4);
                cpwait<DPGc - 2>();
                const int t0 = blk * 4;
                SUB0(t0); SUB0(t0 + 1); SUB0(t0 + 2); SUB0(t0 + 3);
            }
            if (lane == 31) strel(progA, c + 1);
        }
        const int rb = rem32 >> 2, rr = rem32 & 3;
        for (int q = 0; q < rb; ++q, ++blk) {
            ISSUEG((blk + DPGc) * 4);
            cpwait<DPGc - 2>();
            const int t0 = blk * 4;
            SUB0(t0); SUB0(t0 + 1); SUB0(t0 + 2); SUB0(t0 + 3);
        }
        cpwait<0>();
        {
            const int t0 = blk * 4;
            if (rr > 0) SUB0(t0);
            if (rr > 1) SUB0(t0 + 1);
            if (rr > 2) SUB0(t0 + 2);
        }
        if (rem32 && lane == 31) strel(progA, ncfull + 1);
    } else {
        for (int c = 0; c < ncfull; ++c) {
            spinwait(progA, c + 1);
            __syncwarp();
            for (int q = 0; q < 8; ++q, ++blk) {
                ISSUEG((blk + DPGc) * 4);
                cpwait<DPGc - 2>();
                const int t0 = blk * 4;
                SUB1(t0); SUB1(t0 + 1); SUB1(t0 + 2); SUB1(t0 + 3);
            }
        }
        if (rem32) {
            spinwait(progA, ncfull + 1);
            __syncwarp();
            const int rb = rem32 >> 2, rr = rem32 & 3;
            for (int q = 0; q < rb; ++q, ++blk) {
                ISSUEG((blk + DPGc) * 4);
                cpwait<DPGc - 2>();
                const int t0 = blk * 4;
                SUB1(t0); SUB1(t0 + 1); SUB1(t0 + 2); SUB1(t0 + 3);
            }
            cpwait<0>();
            const int t0 = blk * 4;
            if (rr > 0) SUB1(t0);
            if (rr > 1) SUB1(t0 + 1);
            if (rr > 2) SUB1(t0 + 2);
        } else {
            cpwait<0>();
        }
    }
#undef SUB0
#undef SUB1
#undef ISSUEG

    // blank-logp sum C_b (warp 0, fixed order -> deterministic)
    float Cacc = 0.0f;
    if (wid == 0) {
#pragma unroll
        for (int j = 0; j < 8; ++j) Cacc += g_Cpart[b * 256 + lane * 8 + j];
#pragma unroll
        for (int o2 = 16; o2; o2 >>= 1) Cacc += __shfl_xor_sync(0xffffffffu, Cacc, o2);
    }

    // epilogue: both halves to smem (ring0 is dead for both warps by now)
    float* sE = sRing[0];
    float* sO = sRing[0] + 260;
#pragma unroll
    for (int j = 0; j < 4; ++j) { sE[pbase + j] = E[j]; sO[pbase + j] = O[j]; }
    if (tid == 63) sE[256] = Eex;                // state 512 (E_256), warp1 lane31
    __syncthreads();
    if (tid == 0) {
        float vb = sE[Ut];                       // alpha_hat[2*Ut]
        float vl = sO[Ut - 1];                   // alpha_hat[2*Ut - 1]
        g_nll[b] = -(fmaxf(vb, vl) + Cacc);
    }
}

// ---------------------------------------------------------------------------
// Kernel 3: reduce to scalar loss (fixed-order, deterministic)
// ---------------------------------------------------------------------------
__global__ void __launch_bounds__(32) finalize_kernel(const int* __restrict__ loglen,
                                                      float* __restrict__ out) {
    int lane = threadIdx.x;
    float s = 0.0f, c = 0.0f;
    for (int bb = lane; bb < Bb; bb += 32) { s += g_nll[bb]; c += (float)loglen[bb]; }
#pragma unroll
    for (int o = 16; o; o >>= 1) {
        s += __shfl_xor_sync(0xffffffffu, s, o);
        c += __shfl_xor_sync(0xffffffffu, c, o);
    }
    if (lane == 0) out[0] = s / c;
}

// ---------------------------------------------------------------------------
extern "C" void kernel_launch(void* const* d_in, const int* in_sizes, int n_in,
                              void* d_out, int out_size) {
    const float* logits  = (const float*)d_in[0];
    const int*   targets = (const int*)d_in[1];
    const int*   loglen  = (const int*)d_in[2];
    const int*   tgtlen  = (const int*)d_in[3];

    gather_kernel<<<dim3(Tt / GB_ROWS, Bb), 256>>>(logits, targets, loglen);
    dp_kernel<<<Bb, 64>>>(targets, loglen, tgtlen);
    finalize_kernel<<<1, 32>>>(loglen, (float*)d_out);
}

// round 9
// speedup vs baseline: 1.1294x; 1.1294x over previous
#include <cuda_runtime.h>
#include <math.h>

#define Bb 64
#define Tt 2048
#define Vv 256
#define Uu 256
#define NEGV (-1e30f)

__device__ float g_d[(size_t)Bb * Tt * 256];   // d[b,t,i] = logits[b,t,tgt[i]] - logits[b,t,0]
__device__ float g_Cpart[Bb * 256];            // per-8-row blank-logp partials
__device__ float g_nll[Bb];

__device__ __forceinline__ void cp16(unsigned sa, const float* g) {
    asm volatile("cp.async.cg.shared.global [%0], [%1], 16;\n" :: "r"(sa), "l"(g) : "memory");
}
__device__ __forceinline__ void cpcommit() {
    asm volatile("cp.async.commit_group;\n" ::: "memory");
}
template<int N> __device__ __forceinline__ void cpwait() {
    asm volatile("cp.async.wait_group %0;\n" :: "n"(N) : "memory");
}
__device__ __forceinline__ void strel(unsigned a, int v) {
    asm volatile("st.release.cta.shared.b32 [%0], %1;" :: "r"(a), "r"(v) : "memory");
}
__device__ __forceinline__ void spinwait(unsigned a, int need) {
    int v;
    do { asm volatile("ld.acquire.cta.shared.b32 %0, [%1];" : "=r"(v) : "r"(a) : "memory"); } while (v < need);
}

// ---------------------------------------------------------------------------
// Kernel 1: fused lse + emission-delta gather + blank-logp partial sums.
// (identical to R4/R7: ~38us)
// ---------------------------------------------------------------------------
#define GB_ROWS 64
__global__ void __launch_bounds__(256) gather_kernel(const float* __restrict__ logits,
                                                     const int*  __restrict__ targets,
                                                     const int*  __restrict__ loglen) {
    __shared__ int   sTgt[Uu];
    __shared__ float sRow[8][4][Vv];

    const int b  = blockIdx.y;
    const int c  = blockIdx.x;
    const int L  = loglen[b];
    const int t0 = c * GB_ROWS;
    if (t0 >= L) return;

    const int tid = threadIdx.x, w = tid >> 5, lane = tid & 31;
    sTgt[tid] = targets[b * Uu + tid];
    __syncthreads();

    const int tbase = t0 + w * 8;
    if (tbase >= L) return;
    int nrows = L - tbase; if (nrows > 8) nrows = 8;

    const float* lg   = logits + ((size_t)b * Tt + tbase) * Vv;
    float*       dOut = g_d    + ((size_t)b * Tt + tbase) * 256;

#pragma unroll
    for (int p = 0; p < 3; ++p) {
        if (p < nrows) {
            unsigned sa = (unsigned)__cvta_generic_to_shared(&sRow[w][p][lane * 8]);
            const float* g = lg + (size_t)p * Vv + lane * 8;
            cp16(sa, g);
            cp16(sa + 16, g + 4);
        }
        cpcommit();
    }

    float cb = 0.0f;
    for (int k = 0; k < nrows; ++k) {
        int pf = k + 3;
        if (pf < nrows) {
            unsigned sa = (unsigned)__cvta_generic_to_shared(&sRow[w][pf & 3][lane * 8]);
            const float* g = lg + (size_t)pf * Vv + lane * 8;
            cp16(sa, g);
            cp16(sa + 16, g + 4);
        }
        cpcommit();
        cpwait<3>();
        __syncwarp();

        const float* r = sRow[w][k & 3];
        float4 v0 = *(const float4*)&r[lane * 4];
        float4 v1 = *(const float4*)&r[128 + lane * 4];
        float s = __expf(v0.x) + __expf(v0.y) + __expf(v0.z) + __expf(v0.w)
                + __expf(v1.x) + __expf(v1.y) + __expf(v1.z) + __expf(v1.w);
#pragma unroll
        for (int o = 16; o; o >>= 1) s += __shfl_xor_sync(0xffffffffu, s, o);
        float lse = __logf(s);
        float r0  = __shfl_sync(0xffffffffu, v0.x, 0);
        cb += r0 - lse;

        int4 tg0 = *(const int4*)&sTgt[lane * 8];
        int4 tg1 = *(const int4*)&sTgt[lane * 8 + 4];
        float4 d0, d1;
        d0.x = r[tg0.x] - r0;  d0.y = r[tg0.y] - r0;
        d0.z = r[tg0.z] - r0;  d0.w = r[tg0.w] - r0;
        d1.x = r[tg1.x] - r0;  d1.y = r[tg1.y] - r0;
        d1.z = r[tg1.z] - r0;  d1.w = r[tg1.w] - r0;

        *(float4*)&dOut[(size_t)k * 256 + lane * 8]     = d0;
        *(float4*)&dOut[(size_t)k * 256 + lane * 8 + 4] = d1;
        __syncwarp();
    }
    if (lane == 0) g_Cpart[b * 256 + (tbase >> 3)] = cb;
}

// ---------------------------------------------------------------------------
// Kernel 2: Viterbi DP, 2 warps per batch with pipeline skew (as R7/R8), but
// with a 64-row ring, 12 cp.async groups in flight, wait_group 10 -> the
// group being waited on was issued 40 steps earlier, dropping the DRAM-
// latency-imposed floor from ~81 to ~33 cyc/step.
// ---------------------------------------------------------------------------
#define DPGc 12
#define RROWS 64                      // ring rows per warp (slot = row & 63)
#define RINGF (RROWS * 128)           // floats per warp ring (32 KB)
__global__ void __launch_bounds__(64, 1) dp_kernel(const int* __restrict__ targets,
                                                   const int* __restrict__ loglen,
                                                   const int* __restrict__ tgtlen) {
    extern __shared__ float sDyn[];
    // layout: ring0 [0,RINGF), ring1 [RINGF,2*RINGF), bnd [2*RINGF, +Tt+8), dump, prog
    float* sBnd  = sDyn + 2 * RINGF;
    float* sDump = sBnd + (Tt + 8);
    int*   sProgP = (int*)(sDump + 32);

    const int tid  = threadIdx.x;
    const int wid  = tid >> 5;
    const int lane = tid & 31;
    const int b    = blockIdx.x;
    const int L    = loglen[b];
    const int Ut   = tgtlen[b];
    const int l4   = lane * 4;
    const int pbase = wid * 128 + l4;            // global pair index base
    const float* __restrict__ emB = g_d + (size_t)b * Tt * 256 + wid * 128;
    float* ring = sDyn + wid * RINGF;
    const unsigned ringB = (unsigned)__cvta_generic_to_shared(ring);
    const unsigned bndB  = (unsigned)__cvta_generic_to_shared(sBnd);
    const unsigned progA = (unsigned)__cvta_generic_to_shared(sProgP);

    if (tid == 0) { *sProgP = 0; sBnd[0] = NEGV; }
    __syncthreads();

    float gate[4];
    {
        int prev = (pbase == 0) ? -1 : targets[b * Uu + pbase - 1];
#pragma unroll
        for (int j = 0; j < 4; ++j) {
            int cur = targets[b * Uu + pbase + j];
            gate[j] = (pbase + j >= 1 && cur != prev) ? 0.0f : NEGV;
            prev = cur;
        }
    }

    float E[4], O[4];
#pragma unroll
    for (int j = 0; j < 4; ++j) { E[j] = NEGV; O[j] = NEGV; }
    if (tid == 0) E[0] = 0.0f;                   // alpha_hat seed
    float Eex = NEGV, pO_cur = NEGV;
    const float pOmask = (lane == 0) ? NEGV : 0.0f;

    // branch-free boundary store: lane31 -> bnd slot, others -> private dump
    const unsigned stBase = (lane == 31) ? bndB
                           : (unsigned)__cvta_generic_to_shared(&sDump[lane]);
    const unsigned stStep = (lane == 31) ? 4u : 0u;

#define ISSUEG(ROW0)                                                          \
    {                                                                         \
        _Pragma("unroll")                                                     \
        for (int r_ = 0; r_ < 4; ++r_) {                                      \
            int row_ = (ROW0) + r_;                                           \
            if (row_ < L) {                                                   \
                unsigned sa_ = ringB + ((((unsigned)row_ & (RROWS-1u)) << 7) + (unsigned)l4) * 4u; \
                cp16(sa_, emB + (size_t)row_ * 256 + l4);                     \
            }                                                                 \
        }                                                                     \
        cpcommit();                                                           \
    }

    // prologue: groups 0..11 (rows 0..47; L >= 1024)
#pragma unroll
    for (int g2 = 0; g2 < DPGc; ++g2) ISSUEG(g2 * 4);
    cpwait<DPGc - 2>();                          // groups 0,1 complete: rows 0..7

    // 4-phase register buffer, prefetch distance 2
    float buf[4][4];
    *(float4*)&buf[0][0] = *(const float4*)(ring + l4);            // row 0
    *(float4*)&buf[1][0] = *(const float4*)(ring + (1 << 7) + l4); // row 1

    const int ncfull = L >> 5;
    const int rem32  = L & 31;
    int blk = 0;

#define SUB0(T)                                                               \
    {                                                                         \
        const float* sp_ = ring + ((((T) + 2) & (RROWS-1)) << 7) + l4;        \
        *(float4*)&buf[((T) + 2) & 3][0] = *(const float4*)sp_;               \
        const float* dv = buf[(T) & 3];                                       \
        float e3 = E[3], o3 = O[3];                                           \
        float O3n = fmaxf(fmaxf(o3, e3), O[2] + gate[3]) + dv[3];             \
        float E3n = fmaxf(e3, O[2]);                                          \
        float nextPO = __shfl_up_sync(0xffffffffu, O3n, 1);                   \
        unsigned dst_ = stBase + (unsigned)((T) + 1) * stStep;                \
        asm volatile("st.shared.b32 [%0], %1;" :: "r"(dst_), "f"(O3n));       \
        float pO = pO_cur;                                                    \
        _Pragma("unroll")                                                     \
        for (int j = 0; j < 3; ++j) {                                         \
            float e = E[j], o = O[j];                                         \
            E[j] = fmaxf(e, pO);                                              \
            O[j] = fmaxf(fmaxf(o, e), pO + gate[j]) + dv[j];                  \
            pO = o;                                                           \
        }                                                                     \
        E[3] = E3n; O[3] = O3n;                                               \
        pO_cur = nextPO + pOmask;                                             \
    }

#define SUB1(T)                                                               \
    {                                                                         \
        const float* sp_ = ring + ((((T) + 2) & (RROWS-1)) << 7) + l4;        \
        *(float4*)&buf[((T) + 2) & 3][0] = *(const float4*)sp_;               \
        float bn = sBnd[(T) + 1];                                             \
        const float* dv = buf[(T) & 3];                                       \
        float e3 = E[3], o3 = O[3];                                           \
        float O3n = fmaxf(fmaxf(o3, e3), O[2] + gate[3]) + dv[3];             \
        float E3n = fmaxf(e3, O[2]);                                          \
        float nextPO = __shfl_up_sync(0xffffffffu, O3n, 1);                   \
        Eex = fmaxf(Eex, o3);                                                 \
        float pO = pO_cur;                                                    \
        _Pragma("unroll")                                                     \
        for (int j = 0; j < 3; ++j) {                                         \
            float e = E[j], o = O[j];                                         \
            E[j] = fmaxf(e, pO);                                              \
            O[j] = fmaxf(fmaxf(o, e), pO + gate[j]) + dv[j];                  \
            pO = o;                                                           \
        }                                                                     \
        E[3] = E3n; O[3] = O3n;                                               \
        pO_cur = (lane == 0) ? bn : nextPO;                                   \
    }

    if (wid == 0) {
        for (int c = 0; c < ncfull; ++c) {
            for (int q = 0; q < 8; ++q, ++blk) {
                ISSUEG((blk + DPGc) * 4);
                cpwait<DPGc - 2>();
                const int t0 = blk * 4;
                SUB0(t0); SUB0(t0 + 1); SUB0(t0 + 2); SUB0(t0 + 3);
            }
            if (lane == 31) strel(progA, c + 1);
        }
        const int rb = rem32 >> 2, rr = rem32 & 3;
        for (int q = 0; q < rb; ++q, ++blk) {
            ISSUEG((blk + DPGc) * 4);
            cpwait<DPGc - 2>();
            const int t0 = blk * 4;
            SUB0(t0); SUB0(t0 + 1); SUB0(t0 + 2); SUB0(t0 + 3);
        }
        cpwait<0>();
        {
            const int t0 = blk * 4;
            if (rr > 0) SUB0(t0);
            if (rr > 1) SUB0(t0 + 1);
            if (rr > 2) SUB0(t0 + 2);
        }
        if (rem32 && lane == 31) strel(progA, ncfull + 1);
    } else {
        for (int c = 0; c < ncfull; ++c) {
            spinwait(progA, c + 1);
            __syncwarp();
            for (int q = 0; q < 8; ++q, ++blk) {
                ISSUEG((blk + DPGc) * 4);
                cpwait<DPGc - 2>();
                const int t0 = blk * 4;
                SUB1(t0); SUB1(t0 + 1); SUB1(t0 + 2); SUB1(t0 + 3);
            }
        }
        if (rem32) {
            spinwait(progA, ncfull + 1);
            __syncwarp();
            const int rb = rem32 >> 2, rr = rem32 & 3;
            for (int q = 0; q < rb; ++q, ++blk) {
                ISSUEG((blk + DPGc) * 4);
                cpwait<DPGc - 2>();
                const int t0 = blk * 4;
                SUB1(t0); SUB1(t0 + 1); SUB1(t0 + 2); SUB1(t0 + 3);
            }
            cpwait<0>();
            const int t0 = blk * 4;
            if (rr > 0) SUB1(t0);
            if (rr > 1) SUB1(t0 + 1);
            if (rr > 2) SUB1(t0 + 2);
        } else {
            cpwait<0>();
        }
    }
#undef SUB0
#undef SUB1
#undef ISSUEG

    // blank-logp sum C_b (warp 0, fixed order -> deterministic)
    float Cacc = 0.0f;
    if (wid == 0) {
#pragma unroll
        for (int j = 0; j < 8; ++j) Cacc += g_Cpart[b * 256 + lane * 8 + j];
#pragma unroll
        for (int o2 = 16; o2; o2 >>= 1) Cacc += __shfl_xor_sync(0xffffffffu, Cacc, o2);
    }

    // epilogue: both halves to smem (ring0 is dead for both warps by now)
    float* sE = sDyn;
    float* sO = sDyn + 260;
#pragma unroll
    for (int j = 0; j < 4; ++j) { sE[pbase + j] = E[j]; sO[pbase + j] = O[j]; }
    if (tid == 63) sE[256] = Eex;                // state 512 (E_256), warp1 lane31
    __syncthreads();
    if (tid == 0) {
        float vb = sE[Ut];                       // alpha_hat[2*Ut]
        float vl = sO[Ut - 1];                   // alpha_hat[2*Ut - 1]
        g_nll[b] = -(fmaxf(vb, vl) + Cacc);
    }
}

// ---------------------------------------------------------------------------
// Kernel 3: reduce to scalar loss (fixed-order, deterministic)
// ---------------------------------------------------------------------------
__global__ void __launch_bounds__(32) finalize_kernel(const int* __restrict__ loglen,
                                                      float* __restrict__ out) {
    int lane = threadIdx.x;
    float s = 0.0f, c = 0.0f;
    for (int bb = lane; bb < Bb; bb += 32) { s += g_nll[bb]; c += (float)loglen[bb]; }
#pragma unroll
    for (int o = 16; o; o >>= 1) {
        s += __shfl_xor_sync(0xffffffffu, s, o);
        c += __shfl_xor_sync(0xffffffffu, c, o);
    }
    if (lane == 0) out[0] = s / c;
}

// ---------------------------------------------------------------------------
extern "C" void kernel_launch(void* const* d_in, const int* in_sizes, int n_in,
                              void* d_out, int out_size) {
    const float* logits  = (const float*)d_in[0];
    const int*   targets = (const int*)d_in[1];
    const int*   loglen  = (const int*)d_in[2];
    const int*   tgtlen  = (const int*)d_in[3];

    const int dpSmem = (2 * RINGF + (Tt + 8) + 32 + 16) * (int)sizeof(float); // ~74 KB
    cudaFuncSetAttribute(dp_kernel, cudaFuncAttributeMaxDynamicSharedMemorySize, dpSmem);

    gather_kernel<<<dim3(Tt / GB_ROWS, Bb), 256>>>(logits, targets, loglen);
    dp_kernel<<<Bb, 64, dpSmem>>>(targets, loglen, tgtlen);
    finalize_kernel<<<1, 32>>>(loglen, (float*)d_out);
}